// round 15
// baseline (speedup 1.0000x reference)
#include <cuda_runtime.h>
#include <cuda_fp16.h>
#include <cstdint>

#define Nn 50000
#define Dd 128
#define Ee 800000
#define EPS_LN 1e-5f
#define SQRT_D 11.313708498984761f
#define CAP 96        // max degree capacity (mean 16, sigma ~4; 20-sigma margin)
#define NBLK 196

// Scratch (static device globals — allocation-free per harness rules)
// Double-buffered x (hi/lo): layer l reads buf (l&1), writes buf ((l+1)&1).
__device__ __half g_xh0[Nn * Dd];
__device__ __half g_xl0[Nn * Dd];
__device__ __half g_xh1[Nn * Dd];
__device__ __half g_xl1[Nn * Dd];
__device__ __half g_bth[3 * 128 * 256];  // W^T hi, [layer][n][k] (k<128:Wl, else Wr)
__device__ int    g_cnt[Nn];
__device__ int    g_col[Nn * CAP];

// ======================= PTX helpers ========================================
__device__ __forceinline__ uint32_t smem_u32(const void* p) {
    uint32_t a;
    asm("{ .reg .u64 t; cvta.to.shared.u64 t, %1; cvt.u32.u64 %0, t; }"
        : "=r"(a) : "l"(p));
    return a;
}
__device__ __forceinline__ void cp16(uint32_t dst, const void* src, int valid) {
    asm volatile("cp.async.ca.shared.global [%0], [%1], 16, %2;"
                 :: "r"(dst),
                    "l"((unsigned long long)__cvta_generic_to_global(src)),
                    "r"(valid ? 16 : 0));
}
#define CP_COMMIT() asm volatile("cp.async.commit_group;" ::: "memory")
#define CP_WAIT0()  asm volatile("cp.async.wait_group 0;" ::: "memory")

__device__ __forceinline__ void ldsm4(uint32_t* r, uint32_t addr) {
    asm volatile("ldmatrix.sync.aligned.m8n8.x4.shared.b16 {%0,%1,%2,%3}, [%4];"
                 : "=r"(r[0]), "=r"(r[1]), "=r"(r[2]), "=r"(r[3]) : "r"(addr));
}
__device__ __forceinline__ void mma16816(float* d, const uint32_t* a,
                                         const uint32_t* b) {
    asm volatile(
        "mma.sync.aligned.m16n8k16.row.col.f32.f16.f16.f32 "
        "{%0,%1,%2,%3}, {%4,%5,%6,%7}, {%8,%9}, {%0,%1,%2,%3};"
        : "+f"(d[0]), "+f"(d[1]), "+f"(d[2]), "+f"(d[3])
        : "r"(a[0]), "r"(a[1]), "r"(a[2]), "r"(a[3]), "r"(b[0]), "r"(b[1]));
}
__device__ __forceinline__ void split_h(float v, __half& hi, __half& lo) {
    hi = __float2half_rn(v);
    lo = __float2half_rn(v - __half2float(hi));
}
__device__ __forceinline__ float2 recon2(const __half* hp, const __half* lp,
                                         size_t off) {
    float2 fh = __half22float2(*(const __half2*)(hp + off));
    float2 fl = __half22float2(*(const __half2*)(lp + off));
    return make_float2(fh.x + fl.x, fh.y + fl.y);
}
__device__ __forceinline__ void acc_u2(uint2 v, float& a0, float& a1,
                                       float& a2, float& a3) {
    float2 f0 = __half22float2(*(const __half2*)&v.x);
    float2 f1 = __half22float2(*(const __half2*)&v.y);
    a0 += f0.x; a1 += f0.y; a2 += f1.x; a3 += f1.y;
}

// ---------------------------------------------------------------------------
// Kernel 1: x = LayerNorm(node_emb * sqrt(D) + pos_table[pos]); emit hi/lo
// into buffer 0.
// ---------------------------------------------------------------------------
__global__ void embed_ln_kernel(const float* __restrict__ ne,
                                const int* __restrict__ pos,
                                const float* __restrict__ ptab,
                                const float* __restrict__ g,
                                const float* __restrict__ b) {
    int w    = (blockIdx.x * blockDim.x + threadIdx.x) >> 5;
    int lane = threadIdx.x & 31;
    if (w >= Nn) return;
    int p = pos[w];
    float4 nv = *(const float4*)(ne   + (size_t)w * Dd + lane * 4);
    float4 pv = *(const float4*)(ptab + (size_t)p * Dd + lane * 4);
    float v0 = fmaf(nv.x, SQRT_D, pv.x);
    float v1 = fmaf(nv.y, SQRT_D, pv.y);
    float v2 = fmaf(nv.z, SQRT_D, pv.z);
    float v3 = fmaf(nv.w, SQRT_D, pv.w);
    float s = v0 + v1 + v2 + v3;
    float q = v0 * v0 + v1 * v1 + v2 * v2 + v3 * v3;
#pragma unroll
    for (int m = 1; m < 32; m <<= 1) {
        s += __shfl_xor_sync(0xffffffffu, s, m);
        q += __shfl_xor_sync(0xffffffffu, q, m);
    }
    float mean = s * (1.0f / 128.0f);
    float rstd = rsqrtf(q * (1.0f / 128.0f) - mean * mean + EPS_LN);
    float4 gv = *(const float4*)(g + lane * 4);
    float4 bv = *(const float4*)(b + lane * 4);
    float4 o;
    o.x = (v0 - mean) * rstd * gv.x + bv.x;
    o.y = (v1 - mean) * rstd * gv.y + bv.y;
    o.z = (v2 - mean) * rstd * gv.z + bv.z;
    o.w = (v3 - mean) * rstd * gv.w + bv.w;
    size_t off = (size_t)w * Dd + lane * 4;
    __half h0, l0, h1, l1, h2, l2, h3, l3;
    split_h(o.x, h0, l0); split_h(o.y, h1, l1);
    split_h(o.z, h2, l2); split_h(o.w, h3, l3);
    *(__half2*)(g_xh0 + off)     = __half2(h0, h1);
    *(__half2*)(g_xh0 + off + 2) = __half2(h2, h3);
    *(__half2*)(g_xl0 + off)     = __half2(l0, l1);
    *(__half2*)(g_xl0 + off + 2) = __half2(l2, l3);
}

// ---------------------------------------------------------------------------
// W^T hi build: all 3 layers, bt[l][n][k] (k<128 -> Wl, else Wr)
// ---------------------------------------------------------------------------
__global__ void wt_kernel(const float* __restrict__ Wl,
                          const float* __restrict__ Wr) {
    int idx = blockIdx.x * blockDim.x + threadIdx.x;  // 3*128*256 = 98304
    if (idx >= 3 * 128 * 256) return;
    int l = idx >> 15;
    int r = idx & 32767;
    int n = r >> 8;
    int k = r & 255;
    float v = (k < 128) ? Wl[(size_t)l * Dd * Dd + k * Dd + n]
                        : Wr[(size_t)l * Dd * Dd + (k - 128) * Dd + n];
    g_bth[idx] = __float2half_rn(v);
}

// ---------------------------------------------------------------------------
// Direct fixed-stride adjacency bucketing (ONE pass; no scans)
// ---------------------------------------------------------------------------
__global__ void zero_cnt_kernel() {
    int i = blockIdx.x * blockDim.x + threadIdx.x;
    if (i < Nn) g_cnt[i] = 0;
}

__global__ void bucket_kernel(const int* __restrict__ edge) {
    int e = blockIdx.x * blockDim.x + threadIdx.x;
    if (e >= Ee) return;
    int src = edge[e];
    int dst = edge[Ee + e];
    int p = atomicAdd(&g_cnt[dst], 1);
    if (p < CAP) g_col[dst * CAP + p] = src;
}

// ---------------------------------------------------------------------------
// FUSED gather + mma.sync fp16-split dual-GEMM + bias+ReLU+residual+LN
// x is DOUBLE-BUFFERED across layers (read buf xsel, write buf !xsel) so
// cross-CTA read/write of x never races.
// Phase 1: each warp gathers 16 of the CTA's 128 rows, splits hi/lo in regs,
//          stores directly into persistent smem A-tiles (chunks 0-3).
// Phase 2: mainloop; chunks 0-3 read persistent A (B streamed); chunks 4-7
//          stream x hi/lo + B double-buffered.
//   acc = [agg|x] @ [Wl;Wr]  via 2-pass split fp16 (ah*bh + al*bh)
//   x_new = LN(relu(acc + bl) + x)
// ---------------------------------------------------------------------------
#define STR_H    40
#define TILE_HB  (128 * STR_H * 2)          // 10240 B per tile
#define AGG_HB   (8 * TILE_HB)              // 81920 B: 4 chunks x {hi,lo}
#define BUF_HB   (3 * TILE_HB)              // 30720 B per streaming buffer
#define SMEM_MMA (AGG_HB + 2 * BUF_HB)      // 143360 B

__global__ void __launch_bounds__(256, 1)
gemm_fused_kernel(int layer, int xsel,
                  const float* __restrict__ bias, const float* __restrict__ lng,
                  const float* __restrict__ lnb, float* __restrict__ dout,
                  int writeOut) {
    extern __shared__ char smem[];
    const uint32_t su = smem_u32(smem);
    const __half* bth = g_bth + (size_t)layer * 128 * 256;
    const __half* xrh = xsel ? g_xh1 : g_xh0;
    const __half* xrl = xsel ? g_xl1 : g_xl0;
    __half* xwh = xsel ? g_xh0 : g_xh1;
    __half* xwl = xsel ? g_xl0 : g_xl1;
    const int t    = threadIdx.x;
    const int wid  = t >> 5;
    const int lane = t & 31;
    const int row0 = blockIdx.x * 128;
    const int mg   = wid & 3;         // m-group: rows mg*32..+31
    const int nh   = wid >> 2;        // n-half : cols nh*64..+63
    const int n0   = nh * 64;

    // staging assignment: rows sr, sr+64; 16B segment sg
    const int sr = t >> 2;
    const int sg = t & 3;

    auto stage = [&](int c) {
        const uint32_t bb = su + AGG_HB + (c & 1) * BUF_HB;
        const int ka = (c & 3) * 32;
#pragma unroll
        for (int rr = 0; rr < 2; ++rr) {
            const int r = sr + rr * 64;
            const int grow = row0 + r;
            const int ok = (grow < Nn);
            const uint32_t dofs = (uint32_t)(r * STR_H + sg * 8) * 2;
            if (c >= 4) {
                const size_t asrc = (size_t)(ok ? grow : 0) * Dd + ka + sg * 8;
                cp16(bb + dofs,           xrh + asrc, ok);
                cp16(bb + TILE_HB + dofs, xrl + asrc, ok);
            }
            const size_t bsrc = (size_t)r * 256 + c * 32 + sg * 8;
            cp16(bb + 2 * TILE_HB + dofs, bth + bsrc, 1);
        }
        CP_COMMIT();
    };

    // kick off B for chunk 0 before the gather phase (overlaps)
    stage(0);

    // ---------------- Phase 1: gather agg into persistent A-tiles ----------
    {
        const __half* xb = xrh + lane * 4;
        const int ch = lane >> 3;           // chunk 0..3 this lane feeds
        const int kk = (lane & 7) * 4;      // k-offset (halfs) within chunk
        for (int rr = 0; rr < 16; ++rr) {
            const int r = wid * 16 + rr;
            const int grow = row0 + r;
            float c0 = 0.f, c1 = 0.f, c2 = 0.f, c3 = 0.f;
            float d0 = 0.f, d1 = 0.f, d2 = 0.f, d3 = 0.f;
            if (grow < Nn) {
                int beg = grow * CAP;
                int deg = min(g_cnt[grow], CAP);
                int end = beg + deg;
                int jb = beg;
                while (jb < end) {
                    int take = min(32, end - jb);
                    int myc = (lane < take) ? __ldg(&g_col[jb + lane]) : 0;
                    int u = 0;
                    for (; u + 3 < take; u += 4) {
                        int s0 = __shfl_sync(0xffffffffu, myc, u);
                        int s1 = __shfl_sync(0xffffffffu, myc, u + 1);
                        int s2 = __shfl_sync(0xffffffffu, myc, u + 2);
                        int s3 = __shfl_sync(0xffffffffu, myc, u + 3);
                        uint2 v0 = *(const uint2*)(xb + (size_t)s0 * Dd);
                        uint2 v1 = *(const uint2*)(xb + (size_t)s1 * Dd);
                        uint2 v2 = *(const uint2*)(xb + (size_t)s2 * Dd);
                        uint2 v3 = *(const uint2*)(xb + (size_t)s3 * Dd);
                        acc_u2(v0, c0, c1, c2, c3);
                        acc_u2(v1, d0, d1, d2, d3);
                        acc_u2(v2, c0, c1, c2, c3);
                        acc_u2(v3, d0, d1, d2, d3);
                    }
                    for (; u < take; ++u) {
                        int s0 = __shfl_sync(0xffffffffu, myc, u);
                        uint2 v0 = *(const uint2*)(xb + (size_t)s0 * Dd);
                        acc_u2(v0, c0, c1, c2, c3);
                    }
                    jb += take;
                }
            }
            float o0 = c0 + d0, o1 = c1 + d1, o2 = c2 + d2, o3 = c3 + d3;
            __half h0, l0, h1, l1, h2, l2, h3, l3;
            split_h(o0, h0, l0); split_h(o1, h1, l1);
            split_h(o2, h2, l2); split_h(o3, h3, l3);
            // hi tile = 2*ch, lo tile = 2*ch+1
            char* hp = smem + (size_t)(2 * ch) * TILE_HB + (r * STR_H + kk) * 2;
            *(__half2*)(hp)     = __half2(h0, h1);
            *(__half2*)(hp + 4) = __half2(h2, h3);
            char* lp = hp + TILE_HB;
            *(__half2*)(lp)     = __half2(l0, l1);
            *(__half2*)(lp + 4) = __half2(l2, l3);
        }
    }
    CP_WAIT0();
    __syncthreads();

    float acc[64];                    // [mt][nt][4]
#pragma unroll
    for (int i = 0; i < 64; ++i) acc[i] = 0.f;

    // ldmatrix lane-address components
    const int aRow = mg * 32 + (lane & 15);           // + mt*16
    const int aCol = (lane >> 4) * 8;                 // + kk
    const int bRow = n0 + (lane & 7) + ((lane >> 4) << 3);  // + g*16
    const int bCol = ((lane >> 3) & 1) * 8;           // + kk

    for (int c = 0; c < 8; ++c) {
        if (c < 7) stage(c + 1);
        const uint32_t ab = (c < 4) ? (su + (uint32_t)(2 * c) * TILE_HB)
                                    : (su + AGG_HB + (c & 1) * BUF_HB);
        const uint32_t bbB = su + AGG_HB + (c & 1) * BUF_HB + 2 * TILE_HB;
#pragma unroll
        for (int kk = 0; kk < 32; kk += 16) {
            uint32_t ah[2][4], al[2][4], bh[4][4];
#pragma unroll
            for (int mt = 0; mt < 2; ++mt) {
                uint32_t ao = (uint32_t)((aRow + mt * 16) * STR_H + aCol + kk) * 2;
                ldsm4(ah[mt], ab + ao);
                ldsm4(al[mt], ab + TILE_HB + ao);
            }
#pragma unroll
            for (int g = 0; g < 4; ++g) {
                uint32_t bo = (uint32_t)((bRow + g * 16) * STR_H + bCol + kk) * 2;
                ldsm4(bh[g], bbB + bo);
            }
#pragma unroll
            for (int mt = 0; mt < 2; ++mt)
#pragma unroll
                for (int g = 0; g < 4; ++g) {
                    float* d0 = &acc[(mt * 8 + 2 * g) * 4];
                    float* d1 = &acc[(mt * 8 + 2 * g + 1) * 4];
                    mma16816(d0, ah[mt], &bh[g][0]);
                    mma16816(d1, ah[mt], &bh[g][2]);
                    mma16816(d0, al[mt], &bh[g][0]);
                    mma16816(d1, al[mt], &bh[g][2]);
                }
        }
        if (c < 7) CP_WAIT0();
        __syncthreads();
    }

    // ------------------- Epilogue: bias+relu+residual+LN -------------------
    float* sred = (float*)smem;            // [128][8]
    float* qred = (float*)(smem + 4096);   // [128][8]

#pragma unroll
    for (int mt = 0; mt < 2; ++mt) {
        const int rl = mg * 32 + mt * 16 + (lane >> 2);
        const int rh = rl + 8;
        const int gl = row0 + rl, gh = row0 + rh;
        float sl = 0.f, ql = 0.f, sh = 0.f, qh = 0.f;
#pragma unroll
        for (int nt = 0; nt < 8; ++nt) {
            const int cc = n0 + nt * 8 + (lane & 3) * 2;
            float2 bi = *(const float2*)(bias + cc);
            float* a = &acc[(mt * 8 + nt) * 4];
            float h0 = fmaxf(a[0] + bi.x, 0.f);
            float h1 = fmaxf(a[1] + bi.y, 0.f);
            float h2 = fmaxf(a[2] + bi.x, 0.f);
            float h3 = fmaxf(a[3] + bi.y, 0.f);
            float2 xl2 = (gl < Nn) ? recon2(xrh, xrl, (size_t)gl * Dd + cc)
                                   : make_float2(0.f, 0.f);
            float2 xh2 = (gh < Nn) ? recon2(xrh, xrl, (size_t)gh * Dd + cc)
                                   : make_float2(0.f, 0.f);
            h0 += xl2.x; h1 += xl2.y; h2 += xh2.x; h3 += xh2.y;
            a[0] = h0; a[1] = h1; a[2] = h2; a[3] = h3;
            sl += h0 + h1; ql += h0 * h0 + h1 * h1;
            sh += h2 + h3; qh += h2 * h2 + h3 * h3;
        }
        sred[rl * 8 + nh * 4 + (lane & 3)] = sl;
        qred[rl * 8 + nh * 4 + (lane & 3)] = ql;
        sred[rh * 8 + nh * 4 + (lane & 3)] = sh;
        qred[rh * 8 + nh * 4 + (lane & 3)] = qh;
    }
    __syncthreads();

#pragma unroll
    for (int mt = 0; mt < 2; ++mt) {
        const int rl = mg * 32 + mt * 16 + (lane >> 2);
        const int rh = rl + 8;
        const int gl = row0 + rl, gh = row0 + rh;
        float s1 = 0.f, q1 = 0.f, s2 = 0.f, q2 = 0.f;
#pragma unroll
        for (int j = 0; j < 8; ++j) {
            s1 += sred[rl * 8 + j]; q1 += qred[rl * 8 + j];
            s2 += sred[rh * 8 + j]; q2 += qred[rh * 8 + j];
        }
        float m1 = s1 * (1.0f / 128.0f);
        float r1 = rsqrtf(q1 * (1.0f / 128.0f) - m1 * m1 + EPS_LN);
        float m2 = s2 * (1.0f / 128.0f);
        float r2 = rsqrtf(q2 * (1.0f / 128.0f) - m2 * m2 + EPS_LN);
#pragma unroll
        for (int nt = 0; nt < 8; ++nt) {
            const int cc = n0 + nt * 8 + (lane & 3) * 2;
            float2 gv = *(const float2*)(lng + cc);
            float2 tv = *(const float2*)(lnb + cc);
            float* a = &acc[(mt * 8 + nt) * 4];
            if (gl < Nn) {
                float o0 = (a[0] - m1) * r1 * gv.x + tv.x;
                float o1 = (a[1] - m1) * r1 * gv.y + tv.y;
                size_t off = (size_t)gl * Dd + cc;
                if (writeOut) {
                    *(float2*)(dout + off) = make_float2(o0, o1);
                } else {
                    __half hh0, ll0, hh1, ll1;
                    split_h(o0, hh0, ll0); split_h(o1, hh1, ll1);
                    *(__half2*)(xwh + off) = __half2(hh0, hh1);
                    *(__half2*)(xwl + off) = __half2(ll0, ll1);
                }
            }
            if (gh < Nn) {
                float o2 = (a[2] - m2) * r2 * gv.x + tv.x;
                float o3 = (a[3] - m2) * r2 * gv.y + tv.y;
                size_t off = (size_t)gh * Dd + cc;
                if (writeOut) {
                    *(float2*)(dout + off) = make_float2(o2, o3);
                } else {
                    __half hh2, ll2, hh3, ll3;
                    split_h(o2, hh2, ll2); split_h(o3, hh3, ll3);
                    *(__half2*)(xwh + off) = __half2(hh2, hh3);
                    *(__half2*)(xwl + off) = __half2(ll2, ll3);
                }
            }
        }
    }
}

// ---------------------------------------------------------------------------
extern "C" void kernel_launch(void* const* d_in, const int* in_sizes, int n_in,
                              void* d_out, int out_size) {
    const float* node_emb  = (const float*)d_in[0];
    const int*   pos       = (const int*)d_in[1];
    const int*   edge      = (const int*)d_in[2];
    const float* pos_table = (const float*)d_in[3];
    const float* Wl        = (const float*)d_in[4];
    const float* bl        = (const float*)d_in[5];
    const float* Wr        = (const float*)d_in[6];
    const float* emb_g     = (const float*)d_in[7];
    const float* emb_b     = (const float*)d_in[8];
    const float* hid_g     = (const float*)d_in[9];
    const float* hid_b     = (const float*)d_in[10];
    float* out = (float*)d_out;

    cudaFuncSetAttribute(gemm_fused_kernel,
                         cudaFuncAttributeMaxDynamicSharedMemorySize, SMEM_MMA);

    // embedding + LN (fp16 hi/lo splits into x buffer 0)
    embed_ln_kernel<<<(Nn * 32 + 255) / 256, 256>>>(node_emb, pos, pos_table,
                                                    emb_g, emb_b);
    // W^T hi for all layers
    wt_kernel<<<(3 * 128 * 256 + 255) / 256, 256>>>(Wl, Wr);
    // Direct adjacency bucketing (single pass)
    zero_cnt_kernel<<<NBLK, 256>>>();
    bucket_kernel<<<(Ee + 255) / 256, 256>>>(edge);

    const int gemm_blocks = (Nn + 127) / 128;  // 391
    for (int l = 0; l < 3; ++l) {
        gemm_fused_kernel<<<gemm_blocks, 256, SMEM_MMA>>>(
            l, l & 1, bl + (size_t)l * Dd, hid_g + (size_t)l * Dd,
            hid_b + (size_t)l * Dd, out, l == 2 ? 1 : 0);
    }
}

// round 16
// speedup vs baseline: 2.0417x; 2.0417x over previous
#include <cuda_runtime.h>
#include <cuda_fp16.h>
#include <cstdint>

#define Nn 50000
#define Dd 128
#define Ee 800000
#define EPS_LN 1e-5f
#define SQRT_D 11.313708498984761f
#define CAP 96        // max degree capacity (mean 16, sigma ~4; 20-sigma margin)
#define NBLK 196

// Scratch (static device globals — allocation-free per harness rules)
__device__ __half g_xh[Nn * Dd];     // fp16 hi split of x
__device__ __half g_xl[Nn * Dd];     // fp16 lo split of x
__device__ __half g_aggh[Nn * Dd];   // fp16 hi split of agg
__device__ __half g_aggl[Nn * Dd];   // fp16 lo split of agg
__device__ __half g_bth[3 * 128 * 256];  // W^T hi, [layer][n][k] (k<128:Wl, else Wr)
__device__ int    g_cnt[Nn];
__device__ int    g_col[Nn * CAP];

// ======================= PTX helpers ========================================
__device__ __forceinline__ uint32_t smem_u32(const void* p) {
    uint32_t a;
    asm("{ .reg .u64 t; cvta.to.shared.u64 t, %1; cvt.u32.u64 %0, t; }"
        : "=r"(a) : "l"(p));
    return a;
}
__device__ __forceinline__ void cp16(uint32_t dst, const void* src, int valid) {
    asm volatile("cp.async.ca.shared.global [%0], [%1], 16, %2;"
                 :: "r"(dst),
                    "l"((unsigned long long)__cvta_generic_to_global(src)),
                    "r"(valid ? 16 : 0));
}
#define CP_COMMIT() asm volatile("cp.async.commit_group;" ::: "memory")
#define CP_WAIT0()  asm volatile("cp.async.wait_group 0;" ::: "memory")

__device__ __forceinline__ void ldsm4(uint32_t* r, uint32_t addr) {
    asm volatile("ldmatrix.sync.aligned.m8n8.x4.shared.b16 {%0,%1,%2,%3}, [%4];"
                 : "=r"(r[0]), "=r"(r[1]), "=r"(r[2]), "=r"(r[3]) : "r"(addr));
}
__device__ __forceinline__ void mma16816(float* d, const uint32_t* a,
                                         const uint32_t* b) {
    asm volatile(
        "mma.sync.aligned.m16n8k16.row.col.f32.f16.f16.f32 "
        "{%0,%1,%2,%3}, {%4,%5,%6,%7}, {%8,%9}, {%0,%1,%2,%3};"
        : "+f"(d[0]), "+f"(d[1]), "+f"(d[2]), "+f"(d[3])
        : "r"(a[0]), "r"(a[1]), "r"(a[2]), "r"(a[3]), "r"(b[0]), "r"(b[1]));
}
__device__ __forceinline__ void split_h(float v, __half& hi, __half& lo) {
    hi = __float2half_rn(v);
    lo = __float2half_rn(v - __half2float(hi));
}
__device__ __forceinline__ float2 recon2(const __half* hp, const __half* lp,
                                         size_t off) {
    float2 fh = __half22float2(*(const __half2*)(hp + off));
    float2 fl = __half22float2(*(const __half2*)(lp + off));
    return make_float2(fh.x + fl.x, fh.y + fl.y);
}
__device__ __forceinline__ void acc_u2(uint2 v, float& a0, float& a1,
                                       float& a2, float& a3) {
    float2 f0 = __half22float2(*(const __half2*)&v.x);
    float2 f1 = __half22float2(*(const __half2*)&v.y);
    a0 += f0.x; a1 += f0.y; a2 += f1.x; a3 += f1.y;
}

// ---------------------------------------------------------------------------
// Kernel 1: x = LayerNorm(node_emb * sqrt(D) + pos_table[pos]); emit hi/lo.
// ---------------------------------------------------------------------------
__global__ void embed_ln_kernel(const float* __restrict__ ne,
                                const int* __restrict__ pos,
                                const float* __restrict__ ptab,
                                const float* __restrict__ g,
                                const float* __restrict__ b) {
    int w    = (blockIdx.x * blockDim.x + threadIdx.x) >> 5;
    int lane = threadIdx.x & 31;
    if (w >= Nn) return;
    int p = pos[w];
    float4 nv = *(const float4*)(ne   + (size_t)w * Dd + lane * 4);
    float4 pv = *(const float4*)(ptab + (size_t)p * Dd + lane * 4);
    float v0 = fmaf(nv.x, SQRT_D, pv.x);
    float v1 = fmaf(nv.y, SQRT_D, pv.y);
    float v2 = fmaf(nv.z, SQRT_D, pv.z);
    float v3 = fmaf(nv.w, SQRT_D, pv.w);
    float s = v0 + v1 + v2 + v3;
    float q = v0 * v0 + v1 * v1 + v2 * v2 + v3 * v3;
#pragma unroll
    for (int m = 1; m < 32; m <<= 1) {
        s += __shfl_xor_sync(0xffffffffu, s, m);
        q += __shfl_xor_sync(0xffffffffu, q, m);
    }
    float mean = s * (1.0f / 128.0f);
    float rstd = rsqrtf(q * (1.0f / 128.0f) - mean * mean + EPS_LN);
    float4 gv = *(const float4*)(g + lane * 4);
    float4 bv = *(const float4*)(b + lane * 4);
    float4 o;
    o.x = (v0 - mean) * rstd * gv.x + bv.x;
    o.y = (v1 - mean) * rstd * gv.y + bv.y;
    o.z = (v2 - mean) * rstd * gv.z + bv.z;
    o.w = (v3 - mean) * rstd * gv.w + bv.w;
    size_t off = (size_t)w * Dd + lane * 4;
    __half h0, l0, h1, l1, h2, l2, h3, l3;
    split_h(o.x, h0, l0); split_h(o.y, h1, l1);
    split_h(o.z, h2, l2); split_h(o.w, h3, l3);
    *(__half2*)(g_xh + off)     = __half2(h0, h1);
    *(__half2*)(g_xh + off + 2) = __half2(h2, h3);
    *(__half2*)(g_xl + off)     = __half2(l0, l1);
    *(__half2*)(g_xl + off + 2) = __half2(l2, l3);
}

// ---------------------------------------------------------------------------
// W^T hi build: all 3 layers, bt[l][n][k] (k<128 -> Wl, else Wr)
// ---------------------------------------------------------------------------
__global__ void wt_kernel(const float* __restrict__ Wl,
                          const float* __restrict__ Wr) {
    int idx = blockIdx.x * blockDim.x + threadIdx.x;  // 3*128*256 = 98304
    if (idx >= 3 * 128 * 256) return;
    int l = idx >> 15;
    int r = idx & 32767;
    int n = r >> 8;
    int k = r & 255;
    float v = (k < 128) ? Wl[(size_t)l * Dd * Dd + k * Dd + n]
                        : Wr[(size_t)l * Dd * Dd + (k - 128) * Dd + n];
    g_bth[idx] = __float2half_rn(v);
}

// ---------------------------------------------------------------------------
// Direct fixed-stride adjacency bucketing (ONE pass; no scans)
// ---------------------------------------------------------------------------
__global__ void zero_cnt_kernel() {
    int i = blockIdx.x * blockDim.x + threadIdx.x;
    if (i < Nn) g_cnt[i] = 0;
}

__global__ void bucket_kernel(const int* __restrict__ edge) {
    int e = blockIdx.x * blockDim.x + threadIdx.x;
    if (e >= Ee) return;
    int src = edge[e];
    int dst = edge[Ee + e];
    int p = atomicAdd(&g_cnt[dst], 1);
    if (p < CAP) g_col[dst * CAP + p] = src;
}

// ---------------------------------------------------------------------------
// Aggregate: agg[i] = sum over bucket of xh[col]  (fp16 hi gather, fp32 acc)
// One warp per row; one uint2 LDG.64 per neighbor per lane, MLP=4 unroll.
// ---------------------------------------------------------------------------
__global__ void aggregate_kernel() {
    int w    = (blockIdx.x * blockDim.x + threadIdx.x) >> 5;
    int lane = threadIdx.x & 31;
    if (w >= Nn) return;
    int beg = w * CAP;
    int deg = min(g_cnt[w], CAP);
    int end = beg + deg;
    const __half* xb = g_xh + lane * 4;
    float c0 = 0.f, c1 = 0.f, c2 = 0.f, c3 = 0.f;
    float d0 = 0.f, d1 = 0.f, d2 = 0.f, d3 = 0.f;
    int jb = beg;
    while (jb < end) {
        int take = min(32, end - jb);
        int myc = (lane < take) ? __ldg(&g_col[jb + lane]) : 0;
        int u = 0;
        for (; u + 3 < take; u += 4) {
            int s0 = __shfl_sync(0xffffffffu, myc, u);
            int s1 = __shfl_sync(0xffffffffu, myc, u + 1);
            int s2 = __shfl_sync(0xffffffffu, myc, u + 2);
            int s3 = __shfl_sync(0xffffffffu, myc, u + 3);
            uint2 v0 = *(const uint2*)(xb + (size_t)s0 * Dd);
            uint2 v1 = *(const uint2*)(xb + (size_t)s1 * Dd);
            uint2 v2 = *(const uint2*)(xb + (size_t)s2 * Dd);
            uint2 v3 = *(const uint2*)(xb + (size_t)s3 * Dd);
            acc_u2(v0, c0, c1, c2, c3);
            acc_u2(v1, d0, d1, d2, d3);
            acc_u2(v2, c0, c1, c2, c3);
            acc_u2(v3, d0, d1, d2, d3);
        }
        for (; u < take; ++u) {
            int s0 = __shfl_sync(0xffffffffu, myc, u);
            uint2 v0 = *(const uint2*)(xb + (size_t)s0 * Dd);
            acc_u2(v0, c0, c1, c2, c3);
        }
        jb += take;
    }
    float o0 = c0 + d0, o1 = c1 + d1, o2 = c2 + d2, o3 = c3 + d3;
    size_t off = (size_t)w * Dd + lane * 4;
    __half h0, l0, h1, l1, h2, l2, h3, l3;
    split_h(o0, h0, l0); split_h(o1, h1, l1);
    split_h(o2, h2, l2); split_h(o3, h3, l3);
    *(__half2*)(g_aggh + off)     = __half2(h0, h1);
    *(__half2*)(g_aggh + off + 2) = __half2(h2, h3);
    *(__half2*)(g_aggl + off)     = __half2(l0, l1);
    *(__half2*)(g_aggl + off + 2) = __half2(l2, l3);
}

// ---------------------------------------------------------------------------
// mma.sync fp16-split dual-GEMM + bias + ReLU + residual + LayerNorm
//   acc = [agg|x] @ [Wl;Wr]  via 2-pass split fp16 (ah*bh + al*bh)
//   x_new = LN(relu(acc + bl) + x);  residual x reconstructed as hi+lo.
// CTA: 128x128 tile, 256 thr (8 warps, warp = 32x64). K=256 in 8 chunks of 32.
// smem: double-buffered {Ahi,Alo,Bhi}, rows of 40 half (conflict-free LDSM).
// __launch_bounds__(256,2): cap regs at 128/thread so 2 CTAs co-reside per SM
// (smem 61.4KB x 2 fits) — one CTA's staging/epilogue overlaps the other's MMA.
// ---------------------------------------------------------------------------
#define STR_H   40
#define TILE_HB (128 * STR_H * 2)          // 10240 B per tile
#define BUF_HB  (3 * TILE_HB)              // 30720 B per buffer
#define SMEM_MMA (2 * BUF_HB)              // 61440 B

__global__ void __launch_bounds__(256, 2)
gemm_mma_kernel(int layer,
                const float* __restrict__ bias, const float* __restrict__ lng,
                const float* __restrict__ lnb, float* __restrict__ dout,
                int writeOut) {
    extern __shared__ char smem[];
    const uint32_t su = smem_u32(smem);
    const __half* bth = g_bth + (size_t)layer * 128 * 256;
    const int t    = threadIdx.x;
    const int wid  = t >> 5;
    const int lane = t & 31;
    const int row0 = blockIdx.x * 128;
    const int mg   = wid & 3;         // m-group: rows mg*32..+31
    const int nh   = wid >> 2;        // n-half : cols nh*64..+63
    const int n0   = nh * 64;

    // staging assignment: rows sr, sr+64; 16B segment sg
    const int sr = t >> 2;
    const int sg = t & 3;

    float acc[64];                    // [mt][nt][4]
#pragma unroll
    for (int i = 0; i < 64; ++i) acc[i] = 0.f;

    auto stage = [&](int c) {
        const uint32_t bb = su + (c & 1) * BUF_HB;
        const __half* Ah = (c < 4) ? g_aggh : g_xh;
        const __half* Al = (c < 4) ? g_aggl : g_xl;
        const int ka = (c & 3) * 32;
#pragma unroll
        for (int rr = 0; rr < 2; ++rr) {
            const int r = sr + rr * 64;
            const int grow = row0 + r;
            const int ok = (grow < Nn);
            const size_t asrc = (size_t)(ok ? grow : 0) * Dd + ka + sg * 8;
            const uint32_t dofs = (uint32_t)(r * STR_H + sg * 8) * 2;
            cp16(bb + dofs,             Ah + asrc, ok);
            cp16(bb + TILE_HB + dofs,   Al + asrc, ok);
            const size_t bsrc = (size_t)r * 256 + c * 32 + sg * 8;
            cp16(bb + 2 * TILE_HB + dofs, bth + bsrc, 1);
        }
        CP_COMMIT();
    };

    // ldmatrix lane-address components
    const int aRow = mg * 32 + (lane & 15);           // + mt*16
    const int aCol = (lane >> 4) * 8;                 // + kk
    const int bRow = n0 + (lane & 7) + ((lane >> 4) << 3);  // + g*16
    const int bCol = ((lane >> 3) & 1) * 8;           // + kk

    stage(0);
    CP_WAIT0();
    __syncthreads();

    for (int c = 0; c < 8; ++c) {
        const uint32_t bb = su + (c & 1) * BUF_HB;
        if (c < 7) stage(c + 1);
#pragma unroll
        for (int kk = 0; kk < 32; kk += 16) {
            uint32_t ah[2][4], al[2][4], bh[4][4];
#pragma unroll
            for (int mt = 0; mt < 2; ++mt) {
                uint32_t ao = (uint32_t)((aRow + mt * 16) * STR_H + aCol + kk) * 2;
                ldsm4(ah[mt], bb + ao);
                ldsm4(al[mt], bb + TILE_HB + ao);
            }
#pragma unroll
            for (int g = 0; g < 4; ++g) {
                uint32_t bo = (uint32_t)((bRow + g * 16) * STR_H + bCol + kk) * 2;
                ldsm4(bh[g], bb + 2 * TILE_HB + bo);
            }
#pragma unroll
            for (int mt = 0; mt < 2; ++mt)
#pragma unroll
                for (int g = 0; g < 4; ++g) {
                    float* d0 = &acc[(mt * 8 + 2 * g) * 4];
                    float* d1 = &acc[(mt * 8 + 2 * g + 1) * 4];
                    mma16816(d0, ah[mt], &bh[g][0]);
                    mma16816(d1, ah[mt], &bh[g][2]);
                    mma16816(d0, al[mt], &bh[g][0]);
                    mma16816(d1, al[mt], &bh[g][2]);
                }
        }
        if (c < 7) CP_WAIT0();
        __syncthreads();
    }

    // ------------------- Epilogue: bias+relu+residual+LN -------------------
    float* sred = (float*)smem;            // [128][8]
    float* qred = (float*)(smem + 4096);   // [128][8]

#pragma unroll
    for (int mt = 0; mt < 2; ++mt) {
        const int rl = mg * 32 + mt * 16 + (lane >> 2);
        const int rh = rl + 8;
        const int gl = row0 + rl, gh = row0 + rh;
        float sl = 0.f, ql = 0.f, sh = 0.f, qh = 0.f;
#pragma unroll
        for (int nt = 0; nt < 8; ++nt) {
            const int cc = n0 + nt * 8 + (lane & 3) * 2;
            float2 bi = *(const float2*)(bias + cc);
            float* a = &acc[(mt * 8 + nt) * 4];
            float h0 = fmaxf(a[0] + bi.x, 0.f);
            float h1 = fmaxf(a[1] + bi.y, 0.f);
            float h2 = fmaxf(a[2] + bi.x, 0.f);
            float h3 = fmaxf(a[3] + bi.y, 0.f);
            float2 xl2 = (gl < Nn) ? recon2(g_xh, g_xl, (size_t)gl * Dd + cc)
                                   : make_float2(0.f, 0.f);
            float2 xh2 = (gh < Nn) ? recon2(g_xh, g_xl, (size_t)gh * Dd + cc)
                                   : make_float2(0.f, 0.f);
            h0 += xl2.x; h1 += xl2.y; h2 += xh2.x; h3 += xh2.y;
            a[0] = h0; a[1] = h1; a[2] = h2; a[3] = h3;
            sl += h0 + h1; ql += h0 * h0 + h1 * h1;
            sh += h2 + h3; qh += h2 * h2 + h3 * h3;
        }
        sred[rl * 8 + nh * 4 + (lane & 3)] = sl;
        qred[rl * 8 + nh * 4 + (lane & 3)] = ql;
        sred[rh * 8 + nh * 4 + (lane & 3)] = sh;
        qred[rh * 8 + nh * 4 + (lane & 3)] = qh;
    }
    __syncthreads();

#pragma unroll
    for (int mt = 0; mt < 2; ++mt) {
        const int rl = mg * 32 + mt * 16 + (lane >> 2);
        const int rh = rl + 8;
        const int gl = row0 + rl, gh = row0 + rh;
        float s1 = 0.f, q1 = 0.f, s2 = 0.f, q2 = 0.f;
#pragma unroll
        for (int j = 0; j < 8; ++j) {
            s1 += sred[rl * 8 + j]; q1 += qred[rl * 8 + j];
            s2 += sred[rh * 8 + j]; q2 += qred[rh * 8 + j];
        }
        float m1 = s1 * (1.0f / 128.0f);
        float r1 = rsqrtf(q1 * (1.0f / 128.0f) - m1 * m1 + EPS_LN);
        float m2 = s2 * (1.0f / 128.0f);
        float r2 = rsqrtf(q2 * (1.0f / 128.0f) - m2 * m2 + EPS_LN);
#pragma unroll
        for (int nt = 0; nt < 8; ++nt) {
            const int cc = n0 + nt * 8 + (lane & 3) * 2;
            float2 gv = *(const float2*)(lng + cc);
            float2 tv = *(const float2*)(lnb + cc);
            float* a = &acc[(mt * 8 + nt) * 4];
            if (gl < Nn) {
                float o0 = (a[0] - m1) * r1 * gv.x + tv.x;
                float o1 = (a[1] - m1) * r1 * gv.y + tv.y;
                size_t off = (size_t)gl * Dd + cc;
                if (writeOut) {
                    *(float2*)(dout + off) = make_float2(o0, o1);
                } else {
                    __half hh0, ll0, hh1, ll1;
                    split_h(o0, hh0, ll0); split_h(o1, hh1, ll1);
                    *(__half2*)(g_xh + off) = __half2(hh0, hh1);
                    *(__half2*)(g_xl + off) = __half2(ll0, ll1);
                }
            }
            if (gh < Nn) {
                float o2 = (a[2] - m2) * r2 * gv.x + tv.x;
                float o3 = (a[3] - m2) * r2 * gv.y + tv.y;
                size_t off = (size_t)gh * Dd + cc;
                if (writeOut) {
                    *(float2*)(dout + off) = make_float2(o2, o3);
                } else {
                    __half hh2, ll2, hh3, ll3;
                    split_h(o2, hh2, ll2); split_h(o3, hh3, ll3);
                    *(__half2*)(g_xh + off) = __half2(hh2, hh3);
                    *(__half2*)(g_xl + off) = __half2(ll2, ll3);
                }
            }
        }
    }
}

// ---------------------------------------------------------------------------
extern "C" void kernel_launch(void* const* d_in, const int* in_sizes, int n_in,
                              void* d_out, int out_size) {
    const float* node_emb  = (const float*)d_in[0];
    const int*   pos       = (const int*)d_in[1];
    const int*   edge      = (const int*)d_in[2];
    const float* pos_table = (const float*)d_in[3];
    const float* Wl        = (const float*)d_in[4];
    const float* bl        = (const float*)d_in[5];
    const float* Wr        = (const float*)d_in[6];
    const float* emb_g     = (const float*)d_in[7];
    const float* emb_b     = (const float*)d_in[8];
    const float* hid_g     = (const float*)d_in[9];
    const float* hid_b     = (const float*)d_in[10];
    float* out = (float*)d_out;

    cudaFuncSetAttribute(gemm_mma_kernel,
                         cudaFuncAttributeMaxDynamicSharedMemorySize, SMEM_MMA);

    // embedding + LN (fp16 hi/lo splits only)
    embed_ln_kernel<<<(Nn * 32 + 255) / 256, 256>>>(node_emb, pos, pos_table,
                                                    emb_g, emb_b);
    // W^T hi for all layers
    wt_kernel<<<(3 * 128 * 256 + 255) / 256, 256>>>(Wl, Wr);
    // Direct adjacency bucketing (single pass)
    zero_cnt_kernel<<<NBLK, 256>>>();
    bucket_kernel<<<(Ee + 255) / 256, 256>>>(edge);

    const int gemm_blocks = (Nn + 127) / 128;  // 391
    for (int l = 0; l < 3; ++l) {
        aggregate_kernel<<<(Nn * 32 + 255) / 256, 256>>>();
        gemm_mma_kernel<<<gemm_blocks, 256, SMEM_MMA>>>(
            l, bl + (size_t)l * Dd, hid_g + (size_t)l * Dd,
            hid_b + (size_t)l * Dd, out, l == 2 ? 1 : 0);
    }
}

// round 17
// speedup vs baseline: 2.0624x; 1.0101x over previous
#include <cuda_runtime.h>
#include <cuda_fp16.h>
#include <cstdint>

#define Nn 50000
#define Dd 128
#define Ee 800000
#define EPS_LN 1e-5f
#define SQRT_D 11.313708498984761f
#define CAP 96        // max degree capacity (mean 16, sigma ~4; 20-sigma margin)
#define NBLK 196

// Scratch (static device globals — allocation-free per harness rules)
__device__ __half g_xh[Nn * Dd];     // fp16 hi split of x
__device__ __half g_xl[Nn * Dd];     // fp16 lo split of x
__device__ __half g_aggh[Nn * Dd];   // fp16 hi split of agg
__device__ __half g_aggl[Nn * Dd];   // fp16 lo split of agg
__device__ __half g_bth[3 * 128 * 256];  // W^T hi, [layer][n][k] (k<128:Wl, else Wr)
__device__ int    g_cnt[Nn];
__device__ int    g_col[Nn * CAP];

// ======================= PTX helpers ========================================
__device__ __forceinline__ uint32_t smem_u32(const void* p) {
    uint32_t a;
    asm("{ .reg .u64 t; cvta.to.shared.u64 t, %1; cvt.u32.u64 %0, t; }"
        : "=r"(a) : "l"(p));
    return a;
}
__device__ __forceinline__ void cp16(uint32_t dst, const void* src, int valid) {
    asm volatile("cp.async.ca.shared.global [%0], [%1], 16, %2;"
                 :: "r"(dst),
                    "l"((unsigned long long)__cvta_generic_to_global(src)),
                    "r"(valid ? 16 : 0));
}
#define CP_COMMIT() asm volatile("cp.async.commit_group;" ::: "memory")
#define CP_WAIT0()  asm volatile("cp.async.wait_group 0;" ::: "memory")

__device__ __forceinline__ void ldsm4(uint32_t* r, uint32_t addr) {
    asm volatile("ldmatrix.sync.aligned.m8n8.x4.shared.b16 {%0,%1,%2,%3}, [%4];"
                 : "=r"(r[0]), "=r"(r[1]), "=r"(r[2]), "=r"(r[3]) : "r"(addr));
}
__device__ __forceinline__ void mma16816(float* d, const uint32_t* a,
                                         const uint32_t* b) {
    asm volatile(
        "mma.sync.aligned.m16n8k16.row.col.f32.f16.f16.f32 "
        "{%0,%1,%2,%3}, {%4,%5,%6,%7}, {%8,%9}, {%0,%1,%2,%3};"
        : "+f"(d[0]), "+f"(d[1]), "+f"(d[2]), "+f"(d[3])
        : "r"(a[0]), "r"(a[1]), "r"(a[2]), "r"(a[3]), "r"(b[0]), "r"(b[1]));
}
__device__ __forceinline__ void split_h(float v, __half& hi, __half& lo) {
    hi = __float2half_rn(v);
    lo = __float2half_rn(v - __half2float(hi));
}
__device__ __forceinline__ float2 recon2(const __half* hp, const __half* lp,
                                         size_t off) {
    float2 fh = __half22float2(*(const __half2*)(hp + off));
    float2 fl = __half22float2(*(const __half2*)(lp + off));
    return make_float2(fh.x + fl.x, fh.y + fl.y);
}
__device__ __forceinline__ void acc_u2(uint2 v, float& a0, float& a1,
                                       float& a2, float& a3) {
    float2 f0 = __half22float2(*(const __half2*)&v.x);
    float2 f1 = __half22float2(*(const __half2*)&v.y);
    a0 += f0.x; a1 += f0.y; a2 += f1.x; a3 += f1.y;
}

// ---------------------------------------------------------------------------
// Kernel 1: x = LayerNorm(node_emb * sqrt(D) + pos_table[pos]); emit hi/lo.
// ---------------------------------------------------------------------------
__global__ void embed_ln_kernel(const float* __restrict__ ne,
                                const int* __restrict__ pos,
                                const float* __restrict__ ptab,
                                const float* __restrict__ g,
                                const float* __restrict__ b) {
    int w    = (blockIdx.x * blockDim.x + threadIdx.x) >> 5;
    int lane = threadIdx.x & 31;
    if (w >= Nn) return;
    int p = pos[w];
    float4 nv = *(const float4*)(ne   + (size_t)w * Dd + lane * 4);
    float4 pv = *(const float4*)(ptab + (size_t)p * Dd + lane * 4);
    float v0 = fmaf(nv.x, SQRT_D, pv.x);
    float v1 = fmaf(nv.y, SQRT_D, pv.y);
    float v2 = fmaf(nv.z, SQRT_D, pv.z);
    float v3 = fmaf(nv.w, SQRT_D, pv.w);
    float s = v0 + v1 + v2 + v3;
    float q = v0 * v0 + v1 * v1 + v2 * v2 + v3 * v3;
#pragma unroll
    for (int m = 1; m < 32; m <<= 1) {
        s += __shfl_xor_sync(0xffffffffu, s, m);
        q += __shfl_xor_sync(0xffffffffu, q, m);
    }
    float mean = s * (1.0f / 128.0f);
    float rstd = rsqrtf(q * (1.0f / 128.0f) - mean * mean + EPS_LN);
    float4 gv = *(const float4*)(g + lane * 4);
    float4 bv = *(const float4*)(b + lane * 4);
    float4 o;
    o.x = (v0 - mean) * rstd * gv.x + bv.x;
    o.y = (v1 - mean) * rstd * gv.y + bv.y;
    o.z = (v2 - mean) * rstd * gv.z + bv.z;
    o.w = (v3 - mean) * rstd * gv.w + bv.w;
    size_t off = (size_t)w * Dd + lane * 4;
    __half h0, l0, h1, l1, h2, l2, h3, l3;
    split_h(o.x, h0, l0); split_h(o.y, h1, l1);
    split_h(o.z, h2, l2); split_h(o.w, h3, l3);
    *(__half2*)(g_xh + off)     = __half2(h0, h1);
    *(__half2*)(g_xh + off + 2) = __half2(h2, h3);
    *(__half2*)(g_xl + off)     = __half2(l0, l1);
    *(__half2*)(g_xl + off + 2) = __half2(l2, l3);
}

// ---------------------------------------------------------------------------
// W^T hi build: all 3 layers, bt[l][n][k] (k<128 -> Wl, else Wr)
// ---------------------------------------------------------------------------
__global__ void wt_kernel(const float* __restrict__ Wl,
                          const float* __restrict__ Wr) {
    int idx = blockIdx.x * blockDim.x + threadIdx.x;  // 3*128*256 = 98304
    if (idx >= 3 * 128 * 256) return;
    int l = idx >> 15;
    int r = idx & 32767;
    int n = r >> 8;
    int k = r & 255;
    float v = (k < 128) ? Wl[(size_t)l * Dd * Dd + k * Dd + n]
                        : Wr[(size_t)l * Dd * Dd + (k - 128) * Dd + n];
    g_bth[idx] = __float2half_rn(v);
}

// ---------------------------------------------------------------------------
// Direct fixed-stride adjacency bucketing (ONE pass; no scans)
// ---------------------------------------------------------------------------
__global__ void zero_cnt_kernel() {
    int i = blockIdx.x * blockDim.x + threadIdx.x;
    if (i < Nn) g_cnt[i] = 0;
}

__global__ void bucket_kernel(const int* __restrict__ edge) {
    int e = blockIdx.x * blockDim.x + threadIdx.x;
    if (e >= Ee) return;
    int src = edge[e];
    int dst = edge[Ee + e];
    int p = atomicAdd(&g_cnt[dst], 1);
    if (p < CAP) g_col[dst * CAP + p] = src;
}

// ---------------------------------------------------------------------------
// Aggregate: agg[i] = sum over bucket of xh[col]  (fp16 hi gather, fp32 acc)
// One warp per row; one uint2 LDG.64 per neighbor per lane, MLP=4 unroll.
// ---------------------------------------------------------------------------
__global__ void aggregate_kernel() {
    int w    = (blockIdx.x * blockDim.x + threadIdx.x) >> 5;
    int lane = threadIdx.x & 31;
    if (w >= Nn) return;
    int beg = w * CAP;
    int deg = min(g_cnt[w], CAP);
    int end = beg + deg;
    const __half* xb = g_xh + lane * 4;
    float c0 = 0.f, c1 = 0.f, c2 = 0.f, c3 = 0.f;
    float d0 = 0.f, d1 = 0.f, d2 = 0.f, d3 = 0.f;
    int jb = beg;
    while (jb < end) {
        int take = min(32, end - jb);
        int myc = (lane < take) ? __ldg(&g_col[jb + lane]) : 0;
        int u = 0;
        for (; u + 3 < take; u += 4) {
            int s0 = __shfl_sync(0xffffffffu, myc, u);
            int s1 = __shfl_sync(0xffffffffu, myc, u + 1);
            int s2 = __shfl_sync(0xffffffffu, myc, u + 2);
            int s3 = __shfl_sync(0xffffffffu, myc, u + 3);
            uint2 v0 = *(const uint2*)(xb + (size_t)s0 * Dd);
            uint2 v1 = *(const uint2*)(xb + (size_t)s1 * Dd);
            uint2 v2 = *(const uint2*)(xb + (size_t)s2 * Dd);
            uint2 v3 = *(const uint2*)(xb + (size_t)s3 * Dd);
            acc_u2(v0, c0, c1, c2, c3);
            acc_u2(v1, d0, d1, d2, d3);
            acc_u2(v2, c0, c1, c2, c3);
            acc_u2(v3, d0, d1, d2, d3);
        }
        for (; u < take; ++u) {
            int s0 = __shfl_sync(0xffffffffu, myc, u);
            uint2 v0 = *(const uint2*)(xb + (size_t)s0 * Dd);
            acc_u2(v0, c0, c1, c2, c3);
        }
        jb += take;
    }
    float o0 = c0 + d0, o1 = c1 + d1, o2 = c2 + d2, o3 = c3 + d3;
    size_t off = (size_t)w * Dd + lane * 4;
    __half h0, l0, h1, l1, h2, l2, h3, l3;
    split_h(o0, h0, l0); split_h(o1, h1, l1);
    split_h(o2, h2, l2); split_h(o3, h3, l3);
    *(__half2*)(g_aggh + off)     = __half2(h0, h1);
    *(__half2*)(g_aggh + off + 2) = __half2(h2, h3);
    *(__half2*)(g_aggl + off)     = __half2(l0, l1);
    *(__half2*)(g_aggl + off + 2) = __half2(l2, l3);
}

// ---------------------------------------------------------------------------
// mma.sync fp16-split dual-GEMM + bias + ReLU + residual + LayerNorm
//   acc = [agg|x] @ [Wl;Wr]  via 2-pass split fp16 (ah*bh + al*bh)
//   x_new = LN(relu(acc + bl) + x);  residual x reconstructed as hi+lo.
// CTA: 128x128 tile, 256 thr (8 warps, warp = 32x64). K=256 in 8 chunks of 32.
// smem: double-buffered {Ahi,Alo,Bhi}, rows of 40 half (conflict-free LDSM).
// __launch_bounds__(256,2): 2 CTAs/SM so staging/epilogue overlaps MMA.
// ---------------------------------------------------------------------------
#define STR_H   40
#define TILE_HB (128 * STR_H * 2)          // 10240 B per tile
#define BUF_HB  (3 * TILE_HB)              // 30720 B per buffer
#define SMEM_MMA (2 * BUF_HB)              // 61440 B

__global__ void __launch_bounds__(256, 2)
gemm_mma_kernel(int layer,
                const float* __restrict__ bias, const float* __restrict__ lng,
                const float* __restrict__ lnb, float* __restrict__ dout,
                int writeOut) {
    extern __shared__ char smem[];
    const uint32_t su = smem_u32(smem);
    const __half* bth = g_bth + (size_t)layer * 128 * 256;
    const int t    = threadIdx.x;
    const int wid  = t >> 5;
    const int lane = t & 31;
    const int row0 = blockIdx.x * 128;
    const int mg   = wid & 3;         // m-group: rows mg*32..+31
    const int nh   = wid >> 2;        // n-half : cols nh*64..+63
    const int n0   = nh * 64;

    // staging assignment: rows sr, sr+64; 16B segment sg
    const int sr = t >> 2;
    const int sg = t & 3;

    float acc[64];                    // [mt][nt][4]
#pragma unroll
    for (int i = 0; i < 64; ++i) acc[i] = 0.f;

    auto stage = [&](int c) {
        const uint32_t bb = su + (c & 1) * BUF_HB;
        const __half* Ah = (c < 4) ? g_aggh : g_xh;
        const __half* Al = (c < 4) ? g_aggl : g_xl;
        const int ka = (c & 3) * 32;
#pragma unroll
        for (int rr = 0; rr < 2; ++rr) {
            const int r = sr + rr * 64;
            const int grow = row0 + r;
            const int ok = (grow < Nn);
            const size_t asrc = (size_t)(ok ? grow : 0) * Dd + ka + sg * 8;
            const uint32_t dofs = (uint32_t)(r * STR_H + sg * 8) * 2;
            cp16(bb + dofs,             Ah + asrc, ok);
            cp16(bb + TILE_HB + dofs,   Al + asrc, ok);
            const size_t bsrc = (size_t)r * 256 + c * 32 + sg * 8;
            cp16(bb + 2 * TILE_HB + dofs, bth + bsrc, 1);
        }
        CP_COMMIT();
    };

    // ldmatrix lane-address components
    const int aRow = mg * 32 + (lane & 15);           // + mt*16
    const int aCol = (lane >> 4) * 8;                 // + kk
    const int bRow = n0 + (lane & 7) + ((lane >> 4) << 3);  // + g*16
    const int bCol = ((lane >> 3) & 1) * 8;           // + kk

    stage(0);
    CP_WAIT0();
    __syncthreads();

    for (int c = 0; c < 8; ++c) {
        const uint32_t bb = su + (c & 1) * BUF_HB;
        if (c < 7) stage(c + 1);
#pragma unroll
        for (int kk = 0; kk < 32; kk += 16) {
            uint32_t ah[2][4], al[2][4], bh[4][4];
#pragma unroll
            for (int mt = 0; mt < 2; ++mt) {
                uint32_t ao = (uint32_t)((aRow + mt * 16) * STR_H + aCol + kk) * 2;
                ldsm4(ah[mt], bb + ao);
                ldsm4(al[mt], bb + TILE_HB + ao);
            }
#pragma unroll
            for (int g = 0; g < 4; ++g) {
                uint32_t bo = (uint32_t)((bRow + g * 16) * STR_H + bCol + kk) * 2;
                ldsm4(bh[g], bb + 2 * TILE_HB + bo);
            }
#pragma unroll
            for (int mt = 0; mt < 2; ++mt)
#pragma unroll
                for (int g = 0; g < 4; ++g) {
                    float* d0 = &acc[(mt * 8 + 2 * g) * 4];
                    float* d1 = &acc[(mt * 8 + 2 * g + 1) * 4];
                    mma16816(d0, ah[mt], &bh[g][0]);
                    mma16816(d1, ah[mt], &bh[g][2]);
                    mma16816(d0, al[mt], &bh[g][0]);
                    mma16816(d1, al[mt], &bh[g][2]);
                }
        }
        if (c < 7) CP_WAIT0();
        __syncthreads();
    }

    // ------------------- Epilogue: bias+relu+residual+LN -------------------
    float* sred = (float*)smem;            // [128][8]
    float* qred = (float*)(smem + 4096);   // [128][8]

#pragma unroll
    for (int mt = 0; mt < 2; ++mt) {
        const int rl = mg * 32 + mt * 16 + (lane >> 2);
        const int rh = rl + 8;
        const int gl = row0 + rl, gh = row0 + rh;
        float sl = 0.f, ql = 0.f, sh = 0.f, qh = 0.f;
#pragma unroll
        for (int nt = 0; nt < 8; ++nt) {
            const int cc = n0 + nt * 8 + (lane & 3) * 2;
            float2 bi = *(const float2*)(bias + cc);
            float* a = &acc[(mt * 8 + nt) * 4];
            float h0 = fmaxf(a[0] + bi.x, 0.f);
            float h1 = fmaxf(a[1] + bi.y, 0.f);
            float h2 = fmaxf(a[2] + bi.x, 0.f);
            float h3 = fmaxf(a[3] + bi.y, 0.f);
            float2 xl2 = (gl < Nn) ? recon2(g_xh, g_xl, (size_t)gl * Dd + cc)
                                   : make_float2(0.f, 0.f);
            float2 xh2 = (gh < Nn) ? recon2(g_xh, g_xl, (size_t)gh * Dd + cc)
                                   : make_float2(0.f, 0.f);
            h0 += xl2.x; h1 += xl2.y; h2 += xh2.x; h3 += xh2.y;
            a[0] = h0; a[1] = h1; a[2] = h2; a[3] = h3;
            sl += h0 + h1; ql += h0 * h0 + h1 * h1;
            sh += h2 + h3; qh += h2 * h2 + h3 * h3;
        }
        sred[rl * 8 + nh * 4 + (lane & 3)] = sl;
        qred[rl * 8 + nh * 4 + (lane & 3)] = ql;
        sred[rh * 8 + nh * 4 + (lane & 3)] = sh;
        qred[rh * 8 + nh * 4 + (lane & 3)] = qh;
    }
    __syncthreads();

#pragma unroll
    for (int mt = 0; mt < 2; ++mt) {
        const int rl = mg * 32 + mt * 16 + (lane >> 2);
        const int rh = rl + 8;
        const int gl = row0 + rl, gh = row0 + rh;
        float s1 = 0.f, q1 = 0.f, s2 = 0.f, q2 = 0.f;
#pragma unroll
        for (int j = 0; j < 8; ++j) {
            s1 += sred[rl * 8 + j]; q1 += qred[rl * 8 + j];
            s2 += sred[rh * 8 + j]; q2 += qred[rh * 8 + j];
        }
        float m1 = s1 * (1.0f / 128.0f);
        float r1 = rsqrtf(q1 * (1.0f / 128.0f) - m1 * m1 + EPS_LN);
        float m2 = s2 * (1.0f / 128.0f);
        float r2 = rsqrtf(q2 * (1.0f / 128.0f) - m2 * m2 + EPS_LN);
#pragma unroll
        for (int nt = 0; nt < 8; ++nt) {
            const int cc = n0 + nt * 8 + (lane & 3) * 2;
            float2 gv = *(const float2*)(lng + cc);
            float2 tv = *(const float2*)(lnb + cc);
            float* a = &acc[(mt * 8 + nt) * 4];
            if (gl < Nn) {
                float o0 = (a[0] - m1) * r1 * gv.x + tv.x;
                float o1 = (a[1] - m1) * r1 * gv.y + tv.y;
                size_t off = (size_t)gl * Dd + cc;
                if (writeOut) {
                    *(float2*)(dout + off) = make_float2(o0, o1);
                } else {
                    __half hh0, ll0, hh1, ll1;
                    split_h(o0, hh0, ll0); split_h(o1, hh1, ll1);
                    *(__half2*)(g_xh + off) = __half2(hh0, hh1);
                    *(__half2*)(g_xl + off) = __half2(ll0, ll1);
                }
            }
            if (gh < Nn) {
                float o2 = (a[2] - m2) * r2 * gv.x + tv.x;
                float o3 = (a[3] - m2) * r2 * gv.y + tv.y;
                size_t off = (size_t)gh * Dd + cc;
                if (writeOut) {
                    *(float2*)(dout + off) = make_float2(o2, o3);
                } else {
                    __half hh2, ll2, hh3, ll3;
                    split_h(o2, hh2, ll2); split_h(o3, hh3, ll3);
                    *(__half2*)(g_xh + off) = __half2(hh2, hh3);
                    *(__half2*)(g_xl + off) = __half2(ll2, ll3);
                }
            }
        }
    }
}

// ---------------------------------------------------------------------------
extern "C" void kernel_launch(void* const* d_in, const int* in_sizes, int n_in,
                              void* d_out, int out_size) {
    const float* node_emb  = (const float*)d_in[0];
    const int*   pos       = (const int*)d_in[1];
    const int*   edge      = (const int*)d_in[2];
    const float* pos_table = (const float*)d_in[3];
    const float* Wl        = (const float*)d_in[4];
    const float* bl        = (const float*)d_in[5];
    const float* Wr        = (const float*)d_in[6];
    const float* emb_g     = (const float*)d_in[7];
    const float* emb_b     = (const float*)d_in[8];
    const float* hid_g     = (const float*)d_in[9];
    const float* hid_b     = (const float*)d_in[10];
    float* out = (float*)d_out;

    cudaFuncSetAttribute(gemm_mma_kernel,
                         cudaFuncAttributeMaxDynamicSharedMemorySize, SMEM_MMA);

    // -------- fork the independent preamble branches (graph-capture safe):
    //   branch 0 (main stream): embed_ln          (writes x)
    //   branch A:               wt                (weights only)
    //   branch B:               zero_cnt + bucket (edges only)
    cudaStream_t sA, sB;
    cudaStreamCreateWithFlags(&sA, cudaStreamNonBlocking);
    cudaStreamCreateWithFlags(&sB, cudaStreamNonBlocking);
    cudaEvent_t eRoot, eA, eB;
    cudaEventCreateWithFlags(&eRoot, cudaEventDisableTiming);
    cudaEventCreateWithFlags(&eA, cudaEventDisableTiming);
    cudaEventCreateWithFlags(&eB, cudaEventDisableTiming);

    cudaEventRecord(eRoot, 0);
    cudaStreamWaitEvent(sA, eRoot, 0);
    cudaStreamWaitEvent(sB, eRoot, 0);

    embed_ln_kernel<<<(Nn * 32 + 255) / 256, 256>>>(node_emb, pos, pos_table,
                                                    emb_g, emb_b);
    wt_kernel<<<(3 * 128 * 256 + 255) / 256, 256, 0, sA>>>(Wl, Wr);
    zero_cnt_kernel<<<NBLK, 256, 0, sB>>>();
    bucket_kernel<<<(Ee + 255) / 256, 256, 0, sB>>>(edge);

    cudaEventRecord(eA, sA);
    cudaEventRecord(eB, sB);
    cudaStreamWaitEvent(0, eA, 0);
    cudaStreamWaitEvent(0, eB, 0);

    const int gemm_blocks = (Nn + 127) / 128;  // 391
    for (int l = 0; l < 3; ++l) {
        aggregate_kernel<<<(Nn * 32 + 255) / 256, 256>>>();
        gemm_mma_kernel<<<gemm_blocks, 256, SMEM_MMA>>>(
            l, bl + (size_t)l * Dd, hid_g + (size_t)l * Dd,
            hid_b + (size_t)l * Dd, out, l == 2 ? 1 : 0);
    }

    cudaStreamDestroy(sA);
    cudaStreamDestroy(sB);
    cudaEventDestroy(eRoot);
    cudaEventDestroy(eA);
    cudaEventDestroy(eB);
}